// round 3
// baseline (speedup 1.0000x reference)
#include <cuda_runtime.h>
#include <math.h>

#define NTOK 4096
#define DDIM 1024
#define IDIM 512
#define NEXP 16

// ---------------- scratch (no allocations allowed -> __device__ globals) ---
__device__ int   g_counts[NEXP];
__device__ int   g_tok[NEXP * NTOK];    // token id per (expert, row)
__device__ int   g_slot[NEXP * NTOK];   // top-k rank (0/1) per (expert, row)
__device__ float g_w[NTOK * 2];         // normalized routing weights
__device__ float g_H[(size_t)NTOK * 3 * IDIM];  // hidden per (token, slot) ; slot 2 = shared
__device__ float g_Y[(size_t)NTOK * 3 * DDIM];  // down-proj output per (token, slot)

// ---------------------------------------------------------------- kernels --
__global__ void zero_counts_kernel() {
    if (threadIdx.x < NEXP) g_counts[threadIdx.x] = 0;
}

// One block (256 threads) per token: logits = sigmoid(x@gate_w + b), top-2,
// normalize, scatter (token, rank) into per-expert lists.
__global__ void router_kernel(const float* __restrict__ x,
                              const float* __restrict__ gw,
                              const float* __restrict__ gb) {
    int t = blockIdx.x;
    const float* xr = x + (size_t)t * DDIM;

    float acc[NEXP];
#pragma unroll
    for (int e = 0; e < NEXP; e++) acc[e] = 0.f;

    for (int d = threadIdx.x; d < DDIM; d += 256) {
        float xv = xr[d];
        const float4* wr = (const float4*)(gw + (size_t)d * NEXP);
#pragma unroll
        for (int q = 0; q < 4; q++) {
            float4 w4 = wr[q];
            acc[q * 4 + 0] += xv * w4.x;
            acc[q * 4 + 1] += xv * w4.y;
            acc[q * 4 + 2] += xv * w4.z;
            acc[q * 4 + 3] += xv * w4.w;
        }
    }

    __shared__ float red[8][NEXP];
    int lane = threadIdx.x & 31, wid = threadIdx.x >> 5;
#pragma unroll
    for (int e = 0; e < NEXP; e++) {
#pragma unroll
        for (int o = 16; o > 0; o >>= 1)
            acc[e] += __shfl_xor_sync(0xffffffffu, acc[e], o);
    }
    if (lane == 0) {
#pragma unroll
        for (int e = 0; e < NEXP; e++) red[wid][e] = acc[e];
    }
    __syncthreads();

    if (threadIdx.x == 0) {
        float lg[NEXP];
#pragma unroll
        for (int e = 0; e < NEXP; e++) {
            float s = gb[e];
#pragma unroll
            for (int w = 0; w < 8; w++) s += red[w][e];
            lg[e] = 1.f / (1.f + expf(-s));
        }
        // top-2, ties -> lowest index (strict > scan, matches jax top_k)
        int e0 = 0; float v0 = lg[0];
#pragma unroll
        for (int e = 1; e < NEXP; e++) {
            if (lg[e] > v0) { v0 = lg[e]; e0 = e; }
        }
        int e1 = (e0 == 0) ? 1 : 0; float v1 = lg[e1];
#pragma unroll
        for (int e = 0; e < NEXP; e++) {
            if (e != e0 && lg[e] > v1) { v1 = lg[e]; e1 = e; }
        }
        float inv = 1.f / (v0 + v1);
        g_w[t * 2 + 0] = v0 * inv;
        g_w[t * 2 + 1] = v1 * inv;

        int p0 = atomicAdd(&g_counts[e0], 1);
        g_tok[e0 * NTOK + p0] = t;  g_slot[e0 * NTOK + p0] = 0;
        int p1 = atomicAdd(&g_counts[e1], 1);
        g_tok[e1 * NTOK + p1] = t;  g_slot[e1 * NTOK + p1] = 1;
    }
}

// Grouped GEMM 1: H[(t,slot)] = silu(X_e @ wg) * (X_e @ wu)
// grid: (IDIM/64, NTOK/64, NEXP+1). z == NEXP -> shared expert (all tokens, slot 2).
__global__ void __launch_bounds__(256, 3)
gemm1_kernel(const float* __restrict__ x,
             const float* __restrict__ swg, const float* __restrict__ swu,
             const float* __restrict__ ewg, const float* __restrict__ ewu) {
    int e = blockIdx.z;
    int M = (e == NEXP) ? NTOK : g_counts[e];
    int row0 = blockIdx.y * 64;
    if (row0 >= M) return;
    int col0 = blockIdx.x * 64;

    const float* wg = (e == NEXP) ? swg : ewg + (size_t)e * DDIM * IDIM;
    const float* wu = (e == NEXP) ? swu : ewu + (size_t)e * DDIM * IDIM;

    __shared__ int   s_tok[64];
    __shared__ int   s_hrow[64];
    __shared__ float Xs[64][16];
    __shared__ float Gs[16][64];
    __shared__ float Us[16][64];

    int tid = threadIdx.x;
    if (tid < 64) {
        int r = row0 + tid;
        int t = -1, hr = 0;
        if (r < M) {
            if (e == NEXP) { t = r; hr = t * 3 + 2; }
            else { t = g_tok[e * NTOK + r]; hr = t * 3 + g_slot[e * NTOK + r]; }
        }
        s_tok[tid] = t;
        s_hrow[tid] = hr;
    }
    __syncthreads();

    float accg[4][4], accu[4][4];
#pragma unroll
    for (int i = 0; i < 4; i++)
#pragma unroll
        for (int j = 0; j < 4; j++) { accg[i][j] = 0.f; accu[i][j] = 0.f; }

    int ty = tid >> 4, tx = tid & 15;
    int lr = tid >> 2, kq = tid & 3;    // X tile load coords
    int lk = tid >> 4, cq = tid & 15;   // W tile load coords

    for (int k0 = 0; k0 < DDIM; k0 += 16) {
        int tt = s_tok[lr];
        float4 xv = make_float4(0.f, 0.f, 0.f, 0.f);
        if (tt >= 0) xv = *(const float4*)(x + (size_t)tt * DDIM + k0 + kq * 4);
        *(float4*)(&Xs[lr][kq * 4]) = xv;
        *(float4*)(&Gs[lk][cq * 4]) =
            *(const float4*)(wg + (size_t)(k0 + lk) * IDIM + col0 + cq * 4);
        *(float4*)(&Us[lk][cq * 4]) =
            *(const float4*)(wu + (size_t)(k0 + lk) * IDIM + col0 + cq * 4);
        __syncthreads();

#pragma unroll
        for (int kk = 0; kk < 16; kk++) {
            float a[4], bg[4], bu[4];
#pragma unroll
            for (int i = 0; i < 4; i++) a[i] = Xs[ty * 4 + i][kk];
            *(float4*)bg = *(float4*)(&Gs[kk][tx * 4]);
            *(float4*)bu = *(float4*)(&Us[kk][tx * 4]);
#pragma unroll
            for (int i = 0; i < 4; i++)
#pragma unroll
                for (int j = 0; j < 4; j++) {
                    accg[i][j] += a[i] * bg[j];
                    accu[i][j] += a[i] * bu[j];
                }
        }
        __syncthreads();
    }

#pragma unroll
    for (int i = 0; i < 4; i++) {
        int lrr = ty * 4 + i;
        if (row0 + lrr >= M) continue;
        int hr = s_hrow[lrr];
        float4 o;
        float g, u;
        g = accg[i][0]; u = accu[i][0]; o.x = (g / (1.f + expf(-g))) * u;
        g = accg[i][1]; u = accu[i][1]; o.y = (g / (1.f + expf(-g))) * u;
        g = accg[i][2]; u = accu[i][2]; o.z = (g / (1.f + expf(-g))) * u;
        g = accg[i][3]; u = accu[i][3]; o.w = (g / (1.f + expf(-g))) * u;
        *(float4*)(g_H + (size_t)hr * IDIM + col0 + tx * 4) = o;
    }
}

// Grouped GEMM 2: Y[(t,slot)] = H[(t,slot)] @ wd
// grid: (DDIM/64, NTOK/64, NEXP+1)
__global__ void __launch_bounds__(256, 3)
gemm2_kernel(const float* __restrict__ swd, const float* __restrict__ ewd) {
    int e = blockIdx.z;
    int M = (e == NEXP) ? NTOK : g_counts[e];
    int row0 = blockIdx.y * 64;
    if (row0 >= M) return;
    int col0 = blockIdx.x * 64;

    const float* wd = (e == NEXP) ? swd : ewd + (size_t)e * IDIM * DDIM;

    __shared__ int   s_hrow[64];
    __shared__ float Hs[64][16];
    __shared__ float Bs[16][64];

    int tid = threadIdx.x;
    if (tid < 64) {
        int r = row0 + tid;
        int hr = -1;
        if (r < M) {
            hr = (e == NEXP) ? (r * 3 + 2)
                             : (g_tok[e * NTOK + r] * 3 + g_slot[e * NTOK + r]);
        }
        s_hrow[tid] = hr;
    }
    __syncthreads();

    float acc[4][4];
#pragma unroll
    for (int i = 0; i < 4; i++)
#pragma unroll
        for (int j = 0; j < 4; j++) acc[i][j] = 0.f;

    int ty = tid >> 4, tx = tid & 15;
    int lr = tid >> 2, kq = tid & 3;
    int lk = tid >> 4, cq = tid & 15;

    for (int k0 = 0; k0 < IDIM; k0 += 16) {
        int hr = s_hrow[lr];
        float4 hv = make_float4(0.f, 0.f, 0.f, 0.f);
        if (hr >= 0) hv = *(const float4*)(g_H + (size_t)hr * IDIM + k0 + kq * 4);
        *(float4*)(&Hs[lr][kq * 4]) = hv;
        *(float4*)(&Bs[lk][cq * 4]) =
            *(const float4*)(wd + (size_t)(k0 + lk) * DDIM + col0 + cq * 4);
        __syncthreads();

#pragma unroll
        for (int kk = 0; kk < 16; kk++) {
            float a[4], b[4];
#pragma unroll
            for (int i = 0; i < 4; i++) a[i] = Hs[ty * 4 + i][kk];
            *(float4*)b = *(float4*)(&Bs[kk][tx * 4]);
#pragma unroll
            for (int i = 0; i < 4; i++)
#pragma unroll
                for (int j = 0; j < 4; j++) acc[i][j] += a[i] * b[j];
        }
        __syncthreads();
    }

#pragma unroll
    for (int i = 0; i < 4; i++) {
        int lrr = ty * 4 + i;
        if (row0 + lrr >= M) continue;
        int hr = s_hrow[lrr];
        float4 o;
        o.x = acc[i][0]; o.y = acc[i][1]; o.z = acc[i][2]; o.w = acc[i][3];
        *(float4*)(g_Y + (size_t)hr * DDIM + col0 + tx * 4) = o;
    }
}

// out = x + Y_shared + w0*Y_top0 + w1*Y_top1
__global__ void combine_kernel(const float* __restrict__ x, float* __restrict__ out) {
    int idx = blockIdx.x * blockDim.x + threadIdx.x;  // over NTOK*DDIM/4
    if (idx >= NTOK * DDIM / 4) return;
    int t = idx / (DDIM / 4);
    int dq = idx % (DDIM / 4);
    float w0 = g_w[t * 2 + 0], w1 = g_w[t * 2 + 1];
    float4 xv = ((const float4*)x)[idx];
    float4 y0 = *(const float4*)(g_Y + (size_t)(t * 3 + 0) * DDIM + dq * 4);
    float4 y1 = *(const float4*)(g_Y + (size_t)(t * 3 + 1) * DDIM + dq * 4);
    float4 y2 = *(const float4*)(g_Y + (size_t)(t * 3 + 2) * DDIM + dq * 4);
    float4 o;
    o.x = xv.x + y2.x + w0 * y0.x + w1 * y1.x;
    o.y = xv.y + y2.y + w0 * y0.y + w1 * y1.y;
    o.z = xv.z + y2.z + w0 * y0.z + w1 * y1.z;
    o.w = xv.w + y2.w + w0 * y0.w + w1 * y1.w;
    ((float4*)out)[idx] = o;
}

// ------------------------------------------------------------------ launch --
extern "C" void kernel_launch(void* const* d_in, const int* in_sizes, int n_in,
                              void* d_out, int out_size) {
    const float* x   = (const float*)d_in[0];
    const float* gw  = (const float*)d_in[1];
    const float* gb  = (const float*)d_in[2];
    const float* swg = (const float*)d_in[3];
    const float* swu = (const float*)d_in[4];
    const float* swd = (const float*)d_in[5];
    const float* ewg = (const float*)d_in[6];
    const float* ewu = (const float*)d_in[7];
    const float* ewd = (const float*)d_in[8];
    float* out = (float*)d_out;

    zero_counts_kernel<<<1, 32>>>();
    router_kernel<<<NTOK, 256>>>(x, gw, gb);

    dim3 g1(IDIM / 64, NTOK / 64, NEXP + 1);
    gemm1_kernel<<<g1, 256>>>(x, swg, swu, ewg, ewu);

    dim3 g2(DDIM / 64, NTOK / 64, NEXP + 1);
    gemm2_kernel<<<g2, 256>>>(swd, ewd);

    combine_kernel<<<(NTOK * DDIM / 4 + 255) / 256, 256>>>(x, out);
}

// round 9
// speedup vs baseline: 1.4261x; 1.4261x over previous
#include <cuda_runtime.h>
#include <cuda_bf16.h>
#include <stdint.h>
#include <math.h>

#define NTOK 4096
#define DDIM 1024
#define IDIM 512
#define NEXP 16
#define KC   32      // k elements per chunk
#define ROWB 80      // smem row bytes: 32 bf16 (64B) + 16B pad

// ---------------- scratch (no allocations allowed -> __device__ globals) ---
__device__ int   g_counts[NEXP];
__device__ int   g_tok[NEXP * NTOK];
__device__ int   g_slot[NEXP * NTOK];
__device__ float g_w[NTOK * 2];
__device__ float g_H[(size_t)NTOK * 3 * IDIM];  // hidden per (token,slot); slot2 = shared
__device__ float g_Y[(size_t)NTOK * 3 * DDIM];

// ----------------------------------------------------------- helpers ------
__device__ __forceinline__ void mma16816(float* c, const uint32_t* a, const uint32_t* b) {
    asm volatile(
        "mma.sync.aligned.m16n8k16.row.col.f32.bf16.bf16.f32 "
        "{%0,%1,%2,%3}, {%4,%5,%6,%7}, {%8,%9}, {%0,%1,%2,%3};"
        : "+f"(c[0]), "+f"(c[1]), "+f"(c[2]), "+f"(c[3])
        : "r"(a[0]), "r"(a[1]), "r"(a[2]), "r"(a[3]), "r"(b[0]), "r"(b[1]));
}

// split two fp32 into packed bf16x2 hi-word / lo-word
__device__ __forceinline__ uint2 splitpair(float x, float y) {
    __nv_bfloat16 hx = __float2bfloat16(x), hy = __float2bfloat16(y);
    __nv_bfloat16 lx = __float2bfloat16(x - __bfloat162float(hx));
    __nv_bfloat16 ly = __float2bfloat16(y - __bfloat162float(hy));
    uint2 r;
    r.x = (uint32_t)__bfloat16_as_ushort(hx) | ((uint32_t)__bfloat16_as_ushort(hy) << 16);
    r.y = (uint32_t)__bfloat16_as_ushort(lx) | ((uint32_t)__bfloat16_as_ushort(ly) << 16);
    return r;
}

// b-fragment pair: elements B[krow][n] (low 16) and B[krow+1][n] (high 16)
__device__ __forceinline__ uint32_t bpair(const char* base, int krow, int n) {
    uint32_t lo = *(const uint16_t*)(base + krow * ROWB + n * 2);
    uint32_t hi = *(const uint16_t*)(base + (krow + 1) * ROWB + n * 2);
    return lo | (hi << 16);
}

// ---------------------------------------------------------------- kernels --
__global__ void zero_counts_kernel() {
    if (threadIdx.x < NEXP) g_counts[threadIdx.x] = 0;
}

__global__ void router_kernel(const float* __restrict__ x,
                              const float* __restrict__ gw,
                              const float* __restrict__ gb) {
    int t = blockIdx.x;
    const float* xr = x + (size_t)t * DDIM;

    float acc[NEXP];
#pragma unroll
    for (int e = 0; e < NEXP; e++) acc[e] = 0.f;

    for (int d = threadIdx.x; d < DDIM; d += 256) {
        float xv = xr[d];
        const float4* wr = (const float4*)(gw + (size_t)d * NEXP);
#pragma unroll
        for (int q = 0; q < 4; q++) {
            float4 w4 = wr[q];
            acc[q * 4 + 0] += xv * w4.x;
            acc[q * 4 + 1] += xv * w4.y;
            acc[q * 4 + 2] += xv * w4.z;
            acc[q * 4 + 3] += xv * w4.w;
        }
    }

    __shared__ float red[8][NEXP];
    int lane = threadIdx.x & 31, wid = threadIdx.x >> 5;
#pragma unroll
    for (int e = 0; e < NEXP; e++) {
#pragma unroll
        for (int o = 16; o > 0; o >>= 1)
            acc[e] += __shfl_xor_sync(0xffffffffu, acc[e], o);
    }
    if (lane == 0) {
#pragma unroll
        for (int e = 0; e < NEXP; e++) red[wid][e] = acc[e];
    }
    __syncthreads();

    if (threadIdx.x == 0) {
        float lg[NEXP];
#pragma unroll
        for (int e = 0; e < NEXP; e++) {
            float s = gb[e];
#pragma unroll
            for (int w = 0; w < 8; w++) s += red[w][e];
            lg[e] = 1.f / (1.f + expf(-s));
        }
        int e0 = 0; float v0 = lg[0];
#pragma unroll
        for (int e = 1; e < NEXP; e++)
            if (lg[e] > v0) { v0 = lg[e]; e0 = e; }
        int e1 = (e0 == 0) ? 1 : 0; float v1 = lg[e1];
#pragma unroll
        for (int e = 0; e < NEXP; e++)
            if (e != e0 && lg[e] > v1) { v1 = lg[e]; e1 = e; }
        float inv = 1.f / (v0 + v1);
        g_w[t * 2 + 0] = v0 * inv;
        g_w[t * 2 + 1] = v1 * inv;

        int p0 = atomicAdd(&g_counts[e0], 1);
        g_tok[e0 * NTOK + p0] = t;  g_slot[e0 * NTOK + p0] = 0;
        int p1 = atomicAdd(&g_counts[e1], 1);
        g_tok[e1 * NTOK + p1] = t;  g_slot[e1 * NTOK + p1] = 1;
    }
}

// ---- grouped GEMM 1: H = silu(X@wg) * (X@wu), split-bf16 3-pass HMMA -----
// grid (IDIM/32, NTOK/128, NEXP+1), 256 threads
__global__ void __launch_bounds__(256)
gemm1_kernel(const float* __restrict__ x,
             const float* __restrict__ swg, const float* __restrict__ swu,
             const float* __restrict__ ewg, const float* __restrict__ ewu) {
    __shared__ __align__(16) char sAh[128 * ROWB];
    __shared__ __align__(16) char sAl[128 * ROWB];
    __shared__ __align__(16) char sBgh[KC * ROWB];
    __shared__ __align__(16) char sBgl[KC * ROWB];
    __shared__ __align__(16) char sBuh[KC * ROWB];
    __shared__ __align__(16) char sBul[KC * ROWB];
    __shared__ int s_tok[128];
    __shared__ int s_hrow[128];

    int e = blockIdx.z;
    int M = (e == NEXP) ? NTOK : g_counts[e];
    int row0 = blockIdx.y * 128;
    if (row0 >= M) return;
    int col0 = blockIdx.x * 32;

    const float* wg = (e == NEXP) ? swg : ewg + (size_t)e * DDIM * IDIM;
    const float* wu = (e == NEXP) ? swu : ewu + (size_t)e * DDIM * IDIM;

    int tid = threadIdx.x, wid = tid >> 5, lane = tid & 31;
    if (tid < 128) {
        int r = row0 + tid;
        int t = -1, hr = 0;
        if (r < M) {
            if (e == NEXP) { t = r; hr = t * 3 + 2; }
            else { t = g_tok[e * NTOK + r]; hr = t * 3 + g_slot[e * NTOK + r]; }
        }
        s_tok[tid] = t;  s_hrow[tid] = hr;
    }
    __syncthreads();

    // loader coords: A = 2 threads/row (16 floats each); B = 8 threads/row
    int arow = tid >> 1, ahalf = tid & 1;
    int btrow = tid >> 3, bcc = tid & 7;
    int atok = s_tok[arow];
    const float* aptr = x + (size_t)((atok < 0) ? 0 : atok) * DDIM + ahalf * 16;
    const float* bgp = wg + (size_t)btrow * IDIM + col0 + bcc * 4;
    const float* bup = wu + (size_t)btrow * IDIM + col0 + bcc * 4;

    float4 aR[4], gR, uR;
#pragma unroll
    for (int j = 0; j < 4; j++) aR[j] = make_float4(0.f, 0.f, 0.f, 0.f);
    // prologue LDG chunk 0
    if (atok >= 0) {
#pragma unroll
        for (int j = 0; j < 4; j++) aR[j] = *(const float4*)(aptr + j * 4);
    }
    gR = *(const float4*)bgp;
    uR = *(const float4*)bup;

    float accG[2][2][4], accU[2][2][4];
#pragma unroll
    for (int a = 0; a < 2; a++)
#pragma unroll
        for (int b = 0; b < 2; b++)
#pragma unroll
            for (int c = 0; c < 4; c++) { accG[a][b][c] = 0.f; accU[a][b][c] = 0.f; }

    int wm = (wid & 3) * 32, wn = (wid >> 2) * 16;
    int grp = lane >> 2, q = lane & 3;

    const int NCHUNK = DDIM / KC;   // 32
    for (int c = 0; c < NCHUNK; c++) {
        // ---- STS (convert + split in-register)
        {
            char* dah = sAh + arow * ROWB + ahalf * 32;
            char* dal = sAl + arow * ROWB + ahalf * 32;
#pragma unroll
            for (int j = 0; j < 4; j++) {
                uint2 p01 = splitpair(aR[j].x, aR[j].y);
                uint2 p23 = splitpair(aR[j].z, aR[j].w);
                *(uint32_t*)(dah + j * 8)     = p01.x;
                *(uint32_t*)(dah + j * 8 + 4) = p23.x;
                *(uint32_t*)(dal + j * 8)     = p01.y;
                *(uint32_t*)(dal + j * 8 + 4) = p23.y;
            }
            int db = btrow * ROWB + bcc * 8;
            uint2 g01 = splitpair(gR.x, gR.y), g23 = splitpair(gR.z, gR.w);
            *(uint32_t*)(sBgh + db)     = g01.x;  *(uint32_t*)(sBgh + db + 4) = g23.x;
            *(uint32_t*)(sBgl + db)     = g01.y;  *(uint32_t*)(sBgl + db + 4) = g23.y;
            uint2 u01 = splitpair(uR.x, uR.y), u23 = splitpair(uR.z, uR.w);
            *(uint32_t*)(sBuh + db)     = u01.x;  *(uint32_t*)(sBuh + db + 4) = u23.x;
            *(uint32_t*)(sBul + db)     = u01.y;  *(uint32_t*)(sBul + db + 4) = u23.y;
        }
        __syncthreads();
        // ---- prefetch next chunk into regs (overlaps with compute)
        if (c + 1 < NCHUNK) {
            int k0 = (c + 1) * KC;
            if (atok >= 0) {
#pragma unroll
                for (int j = 0; j < 4; j++) aR[j] = *(const float4*)(aptr + k0 + j * 4);
            }
            gR = *(const float4*)(bgp + (size_t)k0 * IDIM);
            uR = *(const float4*)(bup + (size_t)k0 * IDIM);
        }
        // ---- compute: 2 k16 steps
#pragma unroll
        for (int kk = 0; kk < 2; kk++) {
            int kb = kk * 16;
            uint32_t ah[8], al[8];
#pragma unroll
            for (int mf = 0; mf < 2; mf++) {
                int rb = wm + mf * 16 + grp;
                int ab = (kb + 2 * q) * 2;
                ah[mf * 4 + 0] = *(const uint32_t*)(sAh + rb * ROWB + ab);
                ah[mf * 4 + 1] = *(const uint32_t*)(sAh + (rb + 8) * ROWB + ab);
                ah[mf * 4 + 2] = *(const uint32_t*)(sAh + rb * ROWB + ab + 16);
                ah[mf * 4 + 3] = *(const uint32_t*)(sAh + (rb + 8) * ROWB + ab + 16);
                al[mf * 4 + 0] = *(const uint32_t*)(sAl + rb * ROWB + ab);
                al[mf * 4 + 1] = *(const uint32_t*)(sAl + (rb + 8) * ROWB + ab);
                al[mf * 4 + 2] = *(const uint32_t*)(sAl + rb * ROWB + ab + 16);
                al[mf * 4 + 3] = *(const uint32_t*)(sAl + (rb + 8) * ROWB + ab + 16);
            }
#pragma unroll
            for (int nf = 0; nf < 2; nf++) {
                int n = wn + nf * 8 + grp;
                int kr0 = kb + 2 * q, kr1 = kb + 8 + 2 * q;
                uint32_t bgh[2] = { bpair(sBgh, kr0, n), bpair(sBgh, kr1, n) };
                uint32_t bgl[2] = { bpair(sBgl, kr0, n), bpair(sBgl, kr1, n) };
                uint32_t buh[2] = { bpair(sBuh, kr0, n), bpair(sBuh, kr1, n) };
                uint32_t bul[2] = { bpair(sBul, kr0, n), bpair(sBul, kr1, n) };
#pragma unroll
                for (int mf = 0; mf < 2; mf++) {
                    mma16816(accG[mf][nf], ah + mf * 4, bgh);
                    mma16816(accG[mf][nf], ah + mf * 4, bgl);
                    mma16816(accG[mf][nf], al + mf * 4, bgh);
                    mma16816(accU[mf][nf], ah + mf * 4, buh);
                    mma16816(accU[mf][nf], ah + mf * 4, bul);
                    mma16816(accU[mf][nf], al + mf * 4, buh);
                }
            }
        }
        __syncthreads();
    }

    // ---- epilogue: SiLU(g)*u -> g_H fp32
#pragma unroll
    for (int mf = 0; mf < 2; mf++)
#pragma unroll
        for (int nf = 0; nf < 2; nf++) {
            float* cg = accG[mf][nf];
            float* cu = accU[mf][nf];
            int ncol = col0 + wn + nf * 8 + 2 * q;
#pragma unroll
            for (int h = 0; h < 2; h++) {
                int lr = wm + mf * 16 + grp + h * 8;
                if (row0 + lr < M) {
                    int hr = s_hrow[lr];
                    float g0 = cg[h * 2 + 0], g1 = cg[h * 2 + 1];
                    float u0 = cu[h * 2 + 0], u1 = cu[h * 2 + 1];
                    float2 o;
                    o.x = g0 / (1.f + expf(-g0)) * u0;
                    o.y = g1 / (1.f + expf(-g1)) * u1;
                    *(float2*)(g_H + (size_t)hr * IDIM + ncol) = o;
                }
            }
        }
}

// ---- grouped GEMM 2: Y = H @ wd, split-bf16 3-pass HMMA -------------------
// grid (DDIM/32, NTOK/128, NEXP+1), 256 threads
__global__ void __launch_bounds__(256)
gemm2_kernel(const float* __restrict__ swd, const float* __restrict__ ewd) {
    __shared__ __align__(16) char sAh[128 * ROWB];
    __shared__ __align__(16) char sAl[128 * ROWB];
    __shared__ __align__(16) char sBh[KC * ROWB];
    __shared__ __align__(16) char sBl[KC * ROWB];
    __shared__ int s_hrow[128];

    int e = blockIdx.z;
    int M = (e == NEXP) ? NTOK : g_counts[e];
    int row0 = blockIdx.y * 128;
    if (row0 >= M) return;
    int col0 = blockIdx.x * 32;

    const float* wd = (e == NEXP) ? swd : ewd + (size_t)e * IDIM * DDIM;

    int tid = threadIdx.x, wid = tid >> 5, lane = tid & 31;
    if (tid < 128) {
        int r = row0 + tid;
        int hr = -1;
        if (r < M) {
            hr = (e == NEXP) ? (r * 3 + 2)
                             : (g_tok[e * NTOK + r] * 3 + g_slot[e * NTOK + r]);
        }
        s_hrow[tid] = hr;
    }
    __syncthreads();

    int arow = tid >> 1, ahalf = tid & 1;
    int btrow = tid >> 3, bcc = tid & 7;
    int ahr = s_hrow[arow];
    const float* aptr = g_H + (size_t)((ahr < 0) ? 0 : ahr) * IDIM + ahalf * 16;
    const float* bdp = wd + (size_t)btrow * DDIM + col0 + bcc * 4;

    float4 aR[4], dR;
#pragma unroll
    for (int j = 0; j < 4; j++) aR[j] = make_float4(0.f, 0.f, 0.f, 0.f);
    if (ahr >= 0) {
#pragma unroll
        for (int j = 0; j < 4; j++) aR[j] = *(const float4*)(aptr + j * 4);
    }
    dR = *(const float4*)bdp;

    float acc[2][2][4];
#pragma unroll
    for (int a = 0; a < 2; a++)
#pragma unroll
        for (int b = 0; b < 2; b++)
#pragma unroll
            for (int c = 0; c < 4; c++) acc[a][b][c] = 0.f;

    int wm = (wid & 3) * 32, wn = (wid >> 2) * 16;
    int grp = lane >> 2, q = lane & 3;

    const int NCHUNK = IDIM / KC;   // 16
    for (int c = 0; c < NCHUNK; c++) {
        {
            char* dah = sAh + arow * ROWB + ahalf * 32;
            char* dal = sAl + arow * ROWB + ahalf * 32;
#pragma unroll
            for (int j = 0; j < 4; j++) {
                uint2 p01 = splitpair(aR[j].x, aR[j].y);
                uint2 p23 = splitpair(aR[j].z, aR[j].w);
                *(uint32_t*)(dah + j * 8)     = p01.x;
                *(uint32_t*)(dah + j * 8 + 4) = p23.x;
                *(uint32_t*)(dal + j * 8)     = p01.y;
                *(uint32_t*)(dal + j * 8 + 4) = p23.y;
            }
            int db = btrow * ROWB + bcc * 8;
            uint2 d01 = splitpair(dR.x, dR.y), d23 = splitpair(dR.z, dR.w);
            *(uint32_t*)(sBh + db)     = d01.x;  *(uint32_t*)(sBh + db + 4) = d23.x;
            *(uint32_t*)(sBl + db)     = d01.y;  *(uint32_t*)(sBl + db + 4) = d23.y;
        }
        __syncthreads();
        if (c + 1 < NCHUNK) {
            int k0 = (c + 1) * KC;
            if (ahr >= 0) {
#pragma unroll
                for (int j = 0; j < 4; j++) aR[j] = *(const float4*)(aptr + k0 + j * 4);
            }
            dR = *(const float4*)(bdp + (size_t)k0 * DDIM);
        }
#pragma unroll
        for (int kk = 0; kk < 2; kk++) {
            int kb = kk * 16;
            uint32_t ah[8], al[8];
#pragma unroll
            for (int mf = 0; mf < 2; mf++) {
                int rb = wm + mf * 16 + grp;
                int ab = (kb + 2 * q) * 2;
                ah[mf * 4 + 0] = *(const uint32_t*)(sAh + rb * ROWB + ab);
                ah[mf * 4 + 1] = *(const uint32_t*)(sAh + (rb + 8) * ROWB + ab);
                ah[mf * 4 + 2] = *(const uint32_t*)(sAh + rb * ROWB + ab + 16);
                ah[mf * 4 + 3] = *(const uint32_t*)(sAh + (rb + 8) * ROWB + ab + 16);
                al[mf * 4 + 0] = *(const uint32_t*)(sAl + rb * ROWB + ab);
                al[mf * 4 + 1] = *(const uint32_t*)(sAl + (rb + 8) * ROWB + ab);
                al[mf * 4 + 2] = *(const uint32_t*)(sAl + rb * ROWB + ab + 16);
                al[mf * 4 + 3] = *(const uint32_t*)(sAl + (rb + 8) * ROWB + ab + 16);
            }
#pragma unroll
            for (int nf = 0; nf < 2; nf++) {
                int n = wn + nf * 8 + grp;
                int kr0 = kb + 2 * q, kr1 = kb + 8 + 2 * q;
                uint32_t bh[2] = { bpair(sBh, kr0, n), bpair(sBh, kr1, n) };
                uint32_t bl[2] = { bpair(sBl, kr0, n), bpair(sBl, kr1, n) };
#pragma unroll
                for (int mf = 0; mf < 2; mf++) {
                    mma16816(acc[mf][nf], ah + mf * 4, bh);
                    mma16816(acc[mf][nf], ah + mf * 4, bl);
                    mma16816(acc[mf][nf], al + mf * 4, bh);
                }
            }
        }
        __syncthreads();
    }

#pragma unroll
    for (int mf = 0; mf < 2; mf++)
#pragma unroll
        for (int nf = 0; nf < 2; nf++) {
            float* cc = acc[mf][nf];
            int ncol = col0 + wn + nf * 8 + 2 * q;
#pragma unroll
            for (int h = 0; h < 2; h++) {
                int lr = wm + mf * 16 + grp + h * 8;
                if (row0 + lr < M) {
                    int hr = s_hrow[lr];
                    float2 o = make_float2(cc[h * 2 + 0], cc[h * 2 + 1]);
                    *(float2*)(g_Y + (size_t)hr * DDIM + ncol) = o;
                }
            }
        }
}

// out = x + Y_shared + w0*Y_top0 + w1*Y_top1
__global__ void combine_kernel(const float* __restrict__ x, float* __restrict__ out) {
    int idx = blockIdx.x * blockDim.x + threadIdx.x;
    if (idx >= NTOK * DDIM / 4) return;
    int t = idx / (DDIM / 4);
    int dq = idx % (DDIM / 4);
    float w0 = g_w[t * 2 + 0], w1 = g_w[t * 2 + 1];
    float4 xv = ((const float4*)x)[idx];
    float4 y0 = *(const float4*)(g_Y + (size_t)(t * 3 + 0) * DDIM + dq * 4);
    float4 y1 = *(const float4*)(g_Y + (size_t)(t * 3 + 1) * DDIM + dq * 4);
    float4 y2 = *(const float4*)(g_Y + (size_t)(t * 3 + 2) * DDIM + dq * 4);
    float4 o;
    o.x = xv.x + y2.x + w0 * y0.x + w1 * y1.x;
    o.y = xv.y + y2.y + w0 * y0.y + w1 * y1.y;
    o.z = xv.z + y2.z + w0 * y0.z + w1 * y1.z;
    o.w = xv.w + y2.w + w0 * y0.w + w1 * y1.w;
    ((float4*)out)[idx] = o;
}

// ------------------------------------------------------------------ launch --
extern "C" void kernel_launch(void* const* d_in, const int* in_sizes, int n_in,
                              void* d_out, int out_size) {
    const float* x   = (const float*)d_in[0];
    const float* gw  = (const float*)d_in[1];
    const float* gb  = (const float*)d_in[2];
    const float* swg = (const float*)d_in[3];
    const float* swu = (const float*)d_in[4];
    const float* swd = (const float*)d_in[5];
    const float* ewg = (const float*)d_in[6];
    const float* ewu = (const float*)d_in[7];
    const float* ewd = (const float*)d_in[8];
    float* out = (float*)d_out;

    zero_counts_kernel<<<1, 32>>>();
    router_kernel<<<NTOK, 256>>>(x, gw, gb);

    gemm1_kernel<<<dim3(IDIM / 32, NTOK / 128, NEXP + 1), 256>>>(x, swg, swu, ewg, ewu);
    gemm2_kernel<<<dim3(DDIM / 32, NTOK / 128, NEXP + 1), 256>>>(swd, ewd);

    combine_kernel<<<(NTOK * DDIM / 4 + 255) / 256, 256>>>(x, out);
}

// round 10
// speedup vs baseline: 1.7043x; 1.1950x over previous
#include <cuda_runtime.h>
#include <cuda_bf16.h>
#include <stdint.h>
#include <math.h>

#define NTOK 4096
#define DDIM 1024
#define IDIM 512
#define NEXP 16
#define KC   32      // k elements per chunk
#define ROWB 80      // padded smem row bytes: 32 bf16 (64B) + 16B pad

// ---------------- scratch (no allocations allowed -> __device__ globals) ---
__device__ int   g_counts[NEXP];
__device__ int   g_tok[NEXP * NTOK];
__device__ int   g_slot[NEXP * NTOK];
__device__ float g_w[NTOK * 2];
__device__ float g_H[(size_t)NTOK * 3 * IDIM];  // hidden per (token,slot); slot2 = shared
__device__ float g_Y[(size_t)NTOK * 3 * DDIM];

// ----------------------------------------------------------- helpers ------
__device__ __forceinline__ uint32_t smem_u32(const void* p) {
    uint32_t a;
    asm("{ .reg .u64 t; cvta.to.shared.u64 t, %1; cvt.u32.u64 %0, t; }"
        : "=r"(a) : "l"(p));
    return a;
}
__device__ __forceinline__ void mma16816(float* c, const uint32_t* a, const uint32_t* b) {
    asm volatile(
        "mma.sync.aligned.m16n8k16.row.col.f32.bf16.bf16.f32 "
        "{%0,%1,%2,%3}, {%4,%5,%6,%7}, {%8,%9}, {%0,%1,%2,%3};"
        : "+f"(c[0]), "+f"(c[1]), "+f"(c[2]), "+f"(c[3])
        : "r"(a[0]), "r"(a[1]), "r"(a[2]), "r"(a[3]), "r"(b[0]), "r"(b[1]));
}
__device__ __forceinline__ void ldsm_x4(uint32_t* r, uint32_t addr) {
    asm volatile("ldmatrix.sync.aligned.m8n8.x4.shared.b16 {%0,%1,%2,%3}, [%4];"
                 : "=r"(r[0]), "=r"(r[1]), "=r"(r[2]), "=r"(r[3]) : "r"(addr));
}
__device__ __forceinline__ void ldsm_x2t(uint32_t* r, uint32_t addr) {
    asm volatile("ldmatrix.sync.aligned.m8n8.x2.trans.shared.b16 {%0,%1}, [%2];"
                 : "=r"(r[0]), "=r"(r[1]) : "r"(addr));
}

// split two fp32 into packed bf16x2 hi-word / lo-word
__device__ __forceinline__ uint2 splitpair(float x, float y) {
    __nv_bfloat16 hx = __float2bfloat16(x), hy = __float2bfloat16(y);
    __nv_bfloat16 lx = __float2bfloat16(x - __bfloat162float(hx));
    __nv_bfloat16 ly = __float2bfloat16(y - __bfloat162float(hy));
    uint2 r;
    r.x = (uint32_t)__bfloat16_as_ushort(hx) | ((uint32_t)__bfloat16_as_ushort(hy) << 16);
    r.y = (uint32_t)__bfloat16_as_ushort(lx) | ((uint32_t)__bfloat16_as_ushort(ly) << 16);
    return r;
}

// ---------------------------------------------------------------- kernels --
__global__ void zero_counts_kernel() {
    if (threadIdx.x < NEXP) g_counts[threadIdx.x] = 0;
}

__global__ void router_kernel(const float* __restrict__ x,
                              const float* __restrict__ gw,
                              const float* __restrict__ gb) {
    int t = blockIdx.x;
    const float* xr = x + (size_t)t * DDIM;

    float acc[NEXP];
#pragma unroll
    for (int e = 0; e < NEXP; e++) acc[e] = 0.f;

    for (int d = threadIdx.x; d < DDIM; d += 256) {
        float xv = xr[d];
        const float4* wr = (const float4*)(gw + (size_t)d * NEXP);
#pragma unroll
        for (int q = 0; q < 4; q++) {
            float4 w4 = wr[q];
            acc[q * 4 + 0] += xv * w4.x;
            acc[q * 4 + 1] += xv * w4.y;
            acc[q * 4 + 2] += xv * w4.z;
            acc[q * 4 + 3] += xv * w4.w;
        }
    }

    __shared__ float red[8][NEXP];
    int lane = threadIdx.x & 31, wid = threadIdx.x >> 5;
#pragma unroll
    for (int e = 0; e < NEXP; e++) {
#pragma unroll
        for (int o = 16; o > 0; o >>= 1)
            acc[e] += __shfl_xor_sync(0xffffffffu, acc[e], o);
    }
    if (lane == 0) {
#pragma unroll
        for (int e = 0; e < NEXP; e++) red[wid][e] = acc[e];
    }
    __syncthreads();

    if (threadIdx.x == 0) {
        float lg[NEXP];
#pragma unroll
        for (int e = 0; e < NEXP; e++) {
            float s = gb[e];
#pragma unroll
            for (int w = 0; w < 8; w++) s += red[w][e];
            lg[e] = 1.f / (1.f + expf(-s));
        }
        int e0 = 0; float v0 = lg[0];
#pragma unroll
        for (int e = 1; e < NEXP; e++)
            if (lg[e] > v0) { v0 = lg[e]; e0 = e; }
        int e1 = (e0 == 0) ? 1 : 0; float v1 = lg[e1];
#pragma unroll
        for (int e = 0; e < NEXP; e++)
            if (e != e0 && lg[e] > v1) { v1 = lg[e]; e1 = e; }
        float inv = 1.f / (v0 + v1);
        g_w[t * 2 + 0] = v0 * inv;
        g_w[t * 2 + 1] = v1 * inv;

        int p0 = atomicAdd(&g_counts[e0], 1);
        g_tok[e0 * NTOK + p0] = t;  g_slot[e0 * NTOK + p0] = 0;
        int p1 = atomicAdd(&g_counts[e1], 1);
        g_tok[e1 * NTOK + p1] = t;  g_slot[e1 * NTOK + p1] = 1;
    }
}

// ---- grouped GEMM 1: H = silu(X@wg) * (X@wu), split-bf16 3-pass HMMA -----
// grid (IDIM/32, NTOK/128, NEXP+1), 256 threads
__global__ void __launch_bounds__(256)
gemm1_kernel(const float* __restrict__ x,
             const float* __restrict__ swg, const float* __restrict__ swu,
             const float* __restrict__ ewg, const float* __restrict__ ewu) {
    __shared__ __align__(16) char sAh[128 * ROWB];
    __shared__ __align__(16) char sAl[128 * ROWB];
    __shared__ __align__(16) char sBgh[KC * ROWB];
    __shared__ __align__(16) char sBgl[KC * ROWB];
    __shared__ __align__(16) char sBuh[KC * ROWB];
    __shared__ __align__(16) char sBul[KC * ROWB];
    __shared__ int s_tok[128];
    __shared__ int s_hrow[128];

    int e = blockIdx.z;
    int M = (e == NEXP) ? NTOK : g_counts[e];
    int row0 = blockIdx.y * 128;
    if (row0 >= M) return;
    int col0 = blockIdx.x * 32;

    const float* wg = (e == NEXP) ? swg : ewg + (size_t)e * DDIM * IDIM;
    const float* wu = (e == NEXP) ? swu : ewu + (size_t)e * DDIM * IDIM;

    int tid = threadIdx.x, wid = tid >> 5, lane = tid & 31;
    if (tid < 128) {
        int r = row0 + tid;
        int t = -1, hr = 0;
        if (r < M) {
            if (e == NEXP) { t = r; hr = t * 3 + 2; }
            else { t = g_tok[e * NTOK + r]; hr = t * 3 + g_slot[e * NTOK + r]; }
        }
        s_tok[tid] = t;  s_hrow[tid] = hr;
    }
    __syncthreads();

    // loader coords: A = 2 threads/row (16 floats each); B = 8 threads/row
    int arow = tid >> 1, ahalf = tid & 1;
    int btrow = tid >> 3, bcc = tid & 7;
    int atok = s_tok[arow];
    const float* aptr = x + (size_t)((atok < 0) ? 0 : atok) * DDIM + ahalf * 16;
    const float* bgp = wg + (size_t)btrow * IDIM + col0 + bcc * 4;
    const float* bup = wu + (size_t)btrow * IDIM + col0 + bcc * 4;

    float4 aR[4], gR, uR;
#pragma unroll
    for (int j = 0; j < 4; j++) aR[j] = make_float4(0.f, 0.f, 0.f, 0.f);
    if (atok >= 0) {
#pragma unroll
        for (int j = 0; j < 4; j++) aR[j] = *(const float4*)(aptr + j * 4);
    }
    gR = *(const float4*)bgp;
    uR = *(const float4*)bup;

    float accG[2][2][4], accU[2][2][4];
#pragma unroll
    for (int a = 0; a < 2; a++)
#pragma unroll
        for (int b = 0; b < 2; b++)
#pragma unroll
            for (int c = 0; c < 4; c++) { accG[a][b][c] = 0.f; accU[a][b][c] = 0.f; }

    int wm = (wid & 3) * 32, wn = (wid >> 2) * 16;
    int grp = lane >> 2, q = lane & 3;

    // ldmatrix shared-space base addresses + lane offsets
    uint32_t uAh = smem_u32(sAh), uAl = smem_u32(sAl);
    uint32_t uBgh = smem_u32(sBgh), uBgl = smem_u32(sBgl);
    uint32_t uBuh = smem_u32(sBuh), uBul = smem_u32(sBul);
    uint32_t aln = (uint32_t)(lane & 15) * ROWB + ((lane >> 4) & 1) * 16;  // A x4 lane offset
    uint32_t bln = (uint32_t)(lane & 15) * ROWB;                           // B x2.trans lane offset

    const int NCHUNK = DDIM / KC;   // 32
    for (int c = 0; c < NCHUNK; c++) {
        // ---- STS (convert + split in-register)
        {
            char* dah = sAh + arow * ROWB + ahalf * 32;
            char* dal = sAl + arow * ROWB + ahalf * 32;
#pragma unroll
            for (int j = 0; j < 4; j++) {
                uint2 p01 = splitpair(aR[j].x, aR[j].y);
                uint2 p23 = splitpair(aR[j].z, aR[j].w);
                *(uint32_t*)(dah + j * 8)     = p01.x;
                *(uint32_t*)(dah + j * 8 + 4) = p23.x;
                *(uint32_t*)(dal + j * 8)     = p01.y;
                *(uint32_t*)(dal + j * 8 + 4) = p23.y;
            }
            int db = btrow * ROWB + bcc * 8;
            uint2 g01 = splitpair(gR.x, gR.y), g23 = splitpair(gR.z, gR.w);
            *(uint32_t*)(sBgh + db)     = g01.x;  *(uint32_t*)(sBgh + db + 4) = g23.x;
            *(uint32_t*)(sBgl + db)     = g01.y;  *(uint32_t*)(sBgl + db + 4) = g23.y;
            uint2 u01 = splitpair(uR.x, uR.y), u23 = splitpair(uR.z, uR.w);
            *(uint32_t*)(sBuh + db)     = u01.x;  *(uint32_t*)(sBuh + db + 4) = u23.x;
            *(uint32_t*)(sBul + db)     = u01.y;  *(uint32_t*)(sBul + db + 4) = u23.y;
        }
        __syncthreads();
        // ---- prefetch next chunk into regs (overlaps with compute)
        if (c + 1 < NCHUNK) {
            int k0 = (c + 1) * KC;
            if (atok >= 0) {
#pragma unroll
                for (int j = 0; j < 4; j++) aR[j] = *(const float4*)(aptr + k0 + j * 4);
            }
            gR = *(const float4*)(bgp + (size_t)k0 * IDIM);
            uR = *(const float4*)(bup + (size_t)k0 * IDIM);
        }
        // ---- compute: 2 k16 steps
#pragma unroll
        for (int kk = 0; kk < 2; kk++) {
            uint32_t kb2 = kk * 32;           // kb*2 bytes into A rows
            uint32_t kbr = kk * 16 * ROWB;    // kb rows into B arrays
            uint32_t ah[8], al[8];
#pragma unroll
            for (int mf = 0; mf < 2; mf++) {
                uint32_t ro = (uint32_t)(wm + mf * 16) * ROWB + aln + kb2;
                ldsm_x4(ah + mf * 4, uAh + ro);
                ldsm_x4(al + mf * 4, uAl + ro);
            }
#pragma unroll
            for (int nf = 0; nf < 2; nf++) {
                uint32_t co = kbr + bln + (uint32_t)(wn + nf * 8) * 2;
                uint32_t bgh[2], bgl[2], buh[2], bul[2];
                ldsm_x2t(bgh, uBgh + co);
                ldsm_x2t(bgl, uBgl + co);
                ldsm_x2t(buh, uBuh + co);
                ldsm_x2t(bul, uBul + co);
#pragma unroll
                for (int mf = 0; mf < 2; mf++) {
                    mma16816(accG[mf][nf], ah + mf * 4, bgh);
                    mma16816(accG[mf][nf], ah + mf * 4, bgl);
                    mma16816(accG[mf][nf], al + mf * 4, bgh);
                    mma16816(accU[mf][nf], ah + mf * 4, buh);
                    mma16816(accU[mf][nf], ah + mf * 4, bul);
                    mma16816(accU[mf][nf], al + mf * 4, buh);
                }
            }
        }
        __syncthreads();
    }

    // ---- epilogue: SiLU(g)*u -> g_H fp32
#pragma unroll
    for (int mf = 0; mf < 2; mf++)
#pragma unroll
        for (int nf = 0; nf < 2; nf++) {
            float* cg = accG[mf][nf];
            float* cu = accU[mf][nf];
            int ncol = col0 + wn + nf * 8 + 2 * q;
#pragma unroll
            for (int h = 0; h < 2; h++) {
                int lr = wm + mf * 16 + grp + h * 8;
                if (row0 + lr < M) {
                    int hr = s_hrow[lr];
                    float g0 = cg[h * 2 + 0], g1 = cg[h * 2 + 1];
                    float u0 = cu[h * 2 + 0], u1 = cu[h * 2 + 1];
                    float2 o;
                    o.x = g0 / (1.f + expf(-g0)) * u0;
                    o.y = g1 / (1.f + expf(-g1)) * u1;
                    *(float2*)(g_H + (size_t)hr * IDIM + ncol) = o;
                }
            }
        }
}

// ---- grouped GEMM 2: Y = H @ wd, split-bf16 3-pass HMMA -------------------
// grid (DDIM/32, NTOK/128, NEXP+1), 256 threads
__global__ void __launch_bounds__(256)
gemm2_kernel(const float* __restrict__ swd, const float* __restrict__ ewd) {
    __shared__ __align__(16) char sAh[128 * ROWB];
    __shared__ __align__(16) char sAl[128 * ROWB];
    __shared__ __align__(16) char sBh[KC * ROWB];
    __shared__ __align__(16) char sBl[KC * ROWB];
    __shared__ int s_hrow[128];

    int e = blockIdx.z;
    int M = (e == NEXP) ? NTOK : g_counts[e];
    int row0 = blockIdx.y * 128;
    if (row0 >= M) return;
    int col0 = blockIdx.x * 32;

    const float* wd = (e == NEXP) ? swd : ewd + (size_t)e * IDIM * DDIM;

    int tid = threadIdx.x, wid = tid >> 5, lane = tid & 31;
    if (tid < 128) {
        int r = row0 + tid;
        int hr = -1;
        if (r < M) {
            hr = (e == NEXP) ? (r * 3 + 2)
                             : (g_tok[e * NTOK + r] * 3 + g_slot[e * NTOK + r]);
        }
        s_hrow[tid] = hr;
    }
    __syncthreads();

    int arow = tid >> 1, ahalf = tid & 1;
    int btrow = tid >> 3, bcc = tid & 7;
    int ahr = s_hrow[arow];
    const float* aptr = g_H + (size_t)((ahr < 0) ? 0 : ahr) * IDIM + ahalf * 16;
    const float* bdp = wd + (size_t)btrow * DDIM + col0 + bcc * 4;

    float4 aR[4], dR;
#pragma unroll
    for (int j = 0; j < 4; j++) aR[j] = make_float4(0.f, 0.f, 0.f, 0.f);
    if (ahr >= 0) {
#pragma unroll
        for (int j = 0; j < 4; j++) aR[j] = *(const float4*)(aptr + j * 4);
    }
    dR = *(const float4*)bdp;

    float acc[2][2][4];
#pragma unroll
    for (int a = 0; a < 2; a++)
#pragma unroll
        for (int b = 0; b < 2; b++)
#pragma unroll
            for (int c = 0; c < 4; c++) acc[a][b][c] = 0.f;

    int wm = (wid & 3) * 32, wn = (wid >> 2) * 16;
    int grp = lane >> 2, q = lane & 3;

    uint32_t uAh = smem_u32(sAh), uAl = smem_u32(sAl);
    uint32_t uBh = smem_u32(sBh), uBl = smem_u32(sBl);
    uint32_t aln = (uint32_t)(lane & 15) * ROWB + ((lane >> 4) & 1) * 16;
    uint32_t bln = (uint32_t)(lane & 15) * ROWB;

    const int NCHUNK = IDIM / KC;   // 16
    for (int c = 0; c < NCHUNK; c++) {
        {
            char* dah = sAh + arow * ROWB + ahalf * 32;
            char* dal = sAl + arow * ROWB + ahalf * 32;
#pragma unroll
            for (int j = 0; j < 4; j++) {
                uint2 p01 = splitpair(aR[j].x, aR[j].y);
                uint2 p23 = splitpair(aR[j].z, aR[j].w);
                *(uint32_t*)(dah + j * 8)     = p01.x;
                *(uint32_t*)(dah + j * 8 + 4) = p23.x;
                *(uint32_t*)(dal + j * 8)     = p01.y;
                *(uint32_t*)(dal + j * 8 + 4) = p23.y;
            }
            int db = btrow * ROWB + bcc * 8;
            uint2 d01 = splitpair(dR.x, dR.y), d23 = splitpair(dR.z, dR.w);
            *(uint32_t*)(sBh + db)     = d01.x;  *(uint32_t*)(sBh + db + 4) = d23.x;
            *(uint32_t*)(sBl + db)     = d01.y;  *(uint32_t*)(sBl + db + 4) = d23.y;
        }
        __syncthreads();
        if (c + 1 < NCHUNK) {
            int k0 = (c + 1) * KC;
            if (ahr >= 0) {
#pragma unroll
                for (int j = 0; j < 4; j++) aR[j] = *(const float4*)(aptr + k0 + j * 4);
            }
            dR = *(const float4*)(bdp + (size_t)k0 * DDIM);
        }
#pragma unroll
        for (int kk = 0; kk < 2; kk++) {
            uint32_t kb2 = kk * 32;
            uint32_t kbr = kk * 16 * ROWB;
            uint32_t ah[8], al[8];
#pragma unroll
            for (int mf = 0; mf < 2; mf++) {
                uint32_t ro = (uint32_t)(wm + mf * 16) * ROWB + aln + kb2;
                ldsm_x4(ah + mf * 4, uAh + ro);
                ldsm_x4(al + mf * 4, uAl + ro);
            }
#pragma unroll
            for (int nf = 0; nf < 2; nf++) {
                uint32_t co = kbr + bln + (uint32_t)(wn + nf * 8) * 2;
                uint32_t bh[2], bl[2];
                ldsm_x2t(bh, uBh + co);
                ldsm_x2t(bl, uBl + co);
#pragma unroll
                for (int mf = 0; mf < 2; mf++) {
                    mma16816(acc[mf][nf], ah + mf * 4, bh);
                    mma16816(acc[mf][nf], ah + mf * 4, bl);
                    mma16816(acc[mf][nf], al + mf * 4, bh);
                }
            }
        }
        __syncthreads();
    }

#pragma unroll
    for (int mf = 0; mf < 2; mf++)
#pragma unroll
        for (int nf = 0; nf < 2; nf++) {
            float* cc = acc[mf][nf];
            int ncol = col0 + wn + nf * 8 + 2 * q;
#pragma unroll
            for (int h = 0; h < 2; h++) {
                int lr = wm + mf * 16 + grp + h * 8;
                if (row0 + lr < M) {
                    int hr = s_hrow[lr];
                    float2 o = make_float2(cc[h * 2 + 0], cc[h * 2 + 1]);
                    *(float2*)(g_Y + (size_t)hr * DDIM + ncol) = o;
                }
            }
        }
}

// out = x + Y_shared + w0*Y_top0 + w1*Y_top1
__global__ void combine_kernel(const float* __restrict__ x, float* __restrict__ out) {
    int idx = blockIdx.x * blockDim.x + threadIdx.x;
    if (idx >= NTOK * DDIM / 4) return;
    int t = idx / (DDIM / 4);
    int dq = idx % (DDIM / 4);
    float w0 = g_w[t * 2 + 0], w1 = g_w[t * 2 + 1];
    float4 xv = ((const float4*)x)[idx];
    float4 y0 = *(const float4*)(g_Y + (size_t)(t * 3 + 0) * DDIM + dq * 4);
    float4 y1 = *(const float4*)(g_Y + (size_t)(t * 3 + 1) * DDIM + dq * 4);
    float4 y2 = *(const float4*)(g_Y + (size_t)(t * 3 + 2) * DDIM + dq * 4);
    float4 o;
    o.x = xv.x + y2.x + w0 * y0.x + w1 * y1.x;
    o.y = xv.y + y2.y + w0 * y0.y + w1 * y1.y;
    o.z = xv.z + y2.z + w0 * y0.z + w1 * y1.z;
    o.w = xv.w + y2.w + w0 * y0.w + w1 * y1.w;
    ((float4*)out)[idx] = o;
}

// ------------------------------------------------------------------ launch --
extern "C" void kernel_launch(void* const* d_in, const int* in_sizes, int n_in,
                              void* d_out, int out_size) {
    const float* x   = (const float*)d_in[0];
    const float* gw  = (const float*)d_in[1];
    const float* gb  = (const float*)d_in[2];
    const float* swg = (const float*)d_in[3];
    const float* swu = (const float*)d_in[4];
    const float* swd = (const float*)d_in[5];
    const float* ewg = (const float*)d_in[6];
    const float* ewu = (const float*)d_in[7];
    const float* ewd = (const float*)d_in[8];
    float* out = (float*)d_out;

    zero_counts_kernel<<<1, 32>>>();
    router_kernel<<<NTOK, 256>>>(x, gw, gb);

    gemm1_kernel<<<dim3(IDIM / 32, NTOK / 128, NEXP + 1), 256>>>(x, swg, swu, ewg, ewu);
    gemm2_kernel<<<dim3(DDIM / 32, NTOK / 128, NEXP + 1), 256>>>(swd, ewd);

    combine_kernel<<<(NTOK * DDIM / 4 + 255) / 256, 256>>>(x, out);
}

// round 17
// speedup vs baseline: 1.8859x; 1.1066x over previous
#include <cuda_runtime.h>
#include <cuda_bf16.h>
#include <stdint.h>
#include <math.h>

#define NTOK 4096
#define DDIM 1024
#define IDIM 512
#define NEXP 16
#define KC    32     // k elements per chunk
#define ROWB  80     // A smem row bytes: 32 bf16 (64B) + 16B pad
#define ROWB2 144    // gemm2 B smem row bytes: 64 bf16 (128B) + 16B pad

// ---------------- scratch (no allocations allowed -> __device__ globals) ---
__device__ int   g_counts[NEXP];
__device__ int   g_tok[NEXP * NTOK];
__device__ int   g_slot[NEXP * NTOK];
__device__ float g_w[NTOK * 2];
__device__ float g_H[(size_t)NTOK * 3 * IDIM];  // hidden per (token,slot); slot2 = shared
__device__ float g_Y[(size_t)NTOK * 3 * DDIM];

// ----------------------------------------------------------- helpers ------
__device__ __forceinline__ uint32_t smem_u32(const void* p) {
    uint32_t a;
    asm("{ .reg .u64 t; cvta.to.shared.u64 t, %1; cvt.u32.u64 %0, t; }"
        : "=r"(a) : "l"(p));
    return a;
}
__device__ __forceinline__ void mma16816(float* c, const uint32_t* a, const uint32_t* b) {
    asm volatile(
        "mma.sync.aligned.m16n8k16.row.col.f32.bf16.bf16.f32 "
        "{%0,%1,%2,%3}, {%4,%5,%6,%7}, {%8,%9}, {%0,%1,%2,%3};"
        : "+f"(c[0]), "+f"(c[1]), "+f"(c[2]), "+f"(c[3])
        : "r"(a[0]), "r"(a[1]), "r"(a[2]), "r"(a[3]), "r"(b[0]), "r"(b[1]));
}
__device__ __forceinline__ void ldsm_x4(uint32_t* r, uint32_t addr) {
    asm volatile("ldmatrix.sync.aligned.m8n8.x4.shared.b16 {%0,%1,%2,%3}, [%4];"
                 : "=r"(r[0]), "=r"(r[1]), "=r"(r[2]), "=r"(r[3]) : "r"(addr));
}
__device__ __forceinline__ void ldsm_x2t(uint32_t* r, uint32_t addr) {
    asm volatile("ldmatrix.sync.aligned.m8n8.x2.trans.shared.b16 {%0,%1}, [%2];"
                 : "=r"(r[0]), "=r"(r[1]) : "r"(addr));
}
// split two fp32 into packed bf16x2 hi-word / lo-word
__device__ __forceinline__ uint2 splitpair(float x, float y) {
    __nv_bfloat16 hx = __float2bfloat16(x), hy = __float2bfloat16(y);
    __nv_bfloat16 lx = __float2bfloat16(x - __bfloat162float(hx));
    __nv_bfloat16 ly = __float2bfloat16(y - __bfloat162float(hy));
    uint2 r;
    r.x = (uint32_t)__bfloat16_as_ushort(hx) | ((uint32_t)__bfloat16_as_ushort(hy) << 16);
    r.y = (uint32_t)__bfloat16_as_ushort(lx) | ((uint32_t)__bfloat16_as_ushort(ly) << 16);
    return r;
}

// ---------------------------------------------------------------- kernels --
__global__ void zero_counts_kernel() {
    if (threadIdx.x < NEXP) g_counts[threadIdx.x] = 0;
}

__global__ void router_kernel(const float* __restrict__ x,
                              const float* __restrict__ gw,
                              const float* __restrict__ gb) {
    int t = blockIdx.x;
    const float* xr = x + (size_t)t * DDIM;
    float acc[NEXP];
#pragma unroll
    for (int e = 0; e < NEXP; e++) acc[e] = 0.f;
    for (int d = threadIdx.x; d < DDIM; d += 256) {
        float xv = xr[d];
        const float4* wr = (const float4*)(gw + (size_t)d * NEXP);
#pragma unroll
        for (int q = 0; q < 4; q++) {
            float4 w4 = wr[q];
            acc[q * 4 + 0] += xv * w4.x;
            acc[q * 4 + 1] += xv * w4.y;
            acc[q * 4 + 2] += xv * w4.z;
            acc[q * 4 + 3] += xv * w4.w;
        }
    }
    __shared__ float red[8][NEXP];
    int lane = threadIdx.x & 31, wid = threadIdx.x >> 5;
#pragma unroll
    for (int e = 0; e < NEXP; e++) {
#pragma unroll
        for (int o = 16; o > 0; o >>= 1)
            acc[e] += __shfl_xor_sync(0xffffffffu, acc[e], o);
    }
    if (lane == 0) {
#pragma unroll
        for (int e = 0; e < NEXP; e++) red[wid][e] = acc[e];
    }
    __syncthreads();
    if (threadIdx.x == 0) {
        float lg[NEXP];
#pragma unroll
        for (int e = 0; e < NEXP; e++) {
            float s = gb[e];
#pragma unroll
            for (int w = 0; w < 8; w++) s += red[w][e];
            lg[e] = 1.f / (1.f + expf(-s));
        }
        int e0 = 0; float v0 = lg[0];
#pragma unroll
        for (int e = 1; e < NEXP; e++)
            if (lg[e] > v0) { v0 = lg[e]; e0 = e; }
        int e1 = (e0 == 0) ? 1 : 0; float v1 = lg[e1];
#pragma unroll
        for (int e = 0; e < NEXP; e++)
            if (e != e0 && lg[e] > v1) { v1 = lg[e]; e1 = e; }
        float inv = 1.f / (v0 + v1);
        g_w[t * 2 + 0] = v0 * inv;
        g_w[t * 2 + 1] = v1 * inv;
        int p0 = atomicAdd(&g_counts[e0], 1);
        g_tok[e0 * NTOK + p0] = t;  g_slot[e0 * NTOK + p0] = 0;
        int p1 = atomicAdd(&g_counts[e1], 1);
        g_tok[e1 * NTOK + p1] = t;  g_slot[e1 * NTOK + p1] = 1;
    }
}

// ---- grouped GEMM 1: H = silu(X@wg) * (X@wu), split-bf16 3-pass HMMA -----
// grid (IDIM/32, NTOK/128, NEXP+1), 256 threads  (unchanged from round 10)
__global__ void __launch_bounds__(256)
gemm1_kernel(const float* __restrict__ x,
             const float* __restrict__ swg, const float* __restrict__ swu,
             const float* __restrict__ ewg, const float* __restrict__ ewu) {
    __shared__ __align__(16) char sAh[128 * ROWB];
    __shared__ __align__(16) char sAl[128 * ROWB];
    __shared__ __align__(16) char sBgh[KC * ROWB];
    __shared__ __align__(16) char sBgl[KC * ROWB];
    __shared__ __align__(16) char sBuh[KC * ROWB];
    __shared__ __align__(16) char sBul[KC * ROWB];
    __shared__ int s_tok[128];
    __shared__ int s_hrow[128];

    int e = blockIdx.z;
    int M = (e == NEXP) ? NTOK : g_counts[e];
    int row0 = blockIdx.y * 128;
    if (row0 >= M) return;
    int col0 = blockIdx.x * 32;

    const float* wg = (e == NEXP) ? swg : ewg + (size_t)e * DDIM * IDIM;
    const float* wu = (e == NEXP) ? swu : ewu + (size_t)e * DDIM * IDIM;

    int tid = threadIdx.x, wid = tid >> 5, lane = tid & 31;
    if (tid < 128) {
        int r = row0 + tid;
        int t = -1, hr = 0;
        if (r < M) {
            if (e == NEXP) { t = r; hr = t * 3 + 2; }
            else { t = g_tok[e * NTOK + r]; hr = t * 3 + g_slot[e * NTOK + r]; }
        }
        s_tok[tid] = t;  s_hrow[tid] = hr;
    }
    __syncthreads();

    int arow = tid >> 1, ahalf = tid & 1;
    int btrow = tid >> 3, bcc = tid & 7;
    int atok = s_tok[arow];
    const float* aptr = x + (size_t)((atok < 0) ? 0 : atok) * DDIM + ahalf * 16;
    const float* bgp = wg + (size_t)btrow * IDIM + col0 + bcc * 4;
    const float* bup = wu + (size_t)btrow * IDIM + col0 + bcc * 4;

    float4 aR[4], gR, uR;
#pragma unroll
    for (int j = 0; j < 4; j++) aR[j] = make_float4(0.f, 0.f, 0.f, 0.f);
    if (atok >= 0) {
#pragma unroll
        for (int j = 0; j < 4; j++) aR[j] = *(const float4*)(aptr + j * 4);
    }
    gR = *(const float4*)bgp;
    uR = *(const float4*)bup;

    float accG[2][2][4], accU[2][2][4];
#pragma unroll
    for (int a = 0; a < 2; a++)
#pragma unroll
        for (int b = 0; b < 2; b++)
#pragma unroll
            for (int c = 0; c < 4; c++) { accG[a][b][c] = 0.f; accU[a][b][c] = 0.f; }

    int wm = (wid & 3) * 32, wn = (wid >> 2) * 16;
    int grp = lane >> 2, q = lane & 3;

    uint32_t uAh = smem_u32(sAh), uAl = smem_u32(sAl);
    uint32_t uBgh = smem_u32(sBgh), uBgl = smem_u32(sBgl);
    uint32_t uBuh = smem_u32(sBuh), uBul = smem_u32(sBul);
    uint32_t aln = (uint32_t)(lane & 15) * ROWB + ((lane >> 4) & 1) * 16;
    uint32_t bln = (uint32_t)(lane & 15) * ROWB;

    const int NCHUNK = DDIM / KC;   // 32
    for (int c = 0; c < NCHUNK; c++) {
        {
            char* dah = sAh + arow * ROWB + ahalf * 32;
            char* dal = sAl + arow * ROWB + ahalf * 32;
#pragma unroll
            for (int j = 0; j < 4; j++) {
                uint2 p01 = splitpair(aR[j].x, aR[j].y);
                uint2 p23 = splitpair(aR[j].z, aR[j].w);
                *(uint32_t*)(dah + j * 8)     = p01.x;
                *(uint32_t*)(dah + j * 8 + 4) = p23.x;
                *(uint32_t*)(dal + j * 8)     = p01.y;
                *(uint32_t*)(dal + j * 8 + 4) = p23.y;
            }
            int db = btrow * ROWB + bcc * 8;
            uint2 g01 = splitpair(gR.x, gR.y), g23 = splitpair(gR.z, gR.w);
            *(uint32_t*)(sBgh + db)     = g01.x;  *(uint32_t*)(sBgh + db + 4) = g23.x;
            *(uint32_t*)(sBgl + db)     = g01.y;  *(uint32_t*)(sBgl + db + 4) = g23.y;
            uint2 u01 = splitpair(uR.x, uR.y), u23 = splitpair(uR.z, uR.w);
            *(uint32_t*)(sBuh + db)     = u01.x;  *(uint32_t*)(sBuh + db + 4) = u23.x;
            *(uint32_t*)(sBul + db)     = u01.y;  *(uint32_t*)(sBul + db + 4) = u23.y;
        }
        __syncthreads();
        if (c + 1 < NCHUNK) {
            int k0 = (c + 1) * KC;
            if (atok >= 0) {
#pragma unroll
                for (int j = 0; j < 4; j++) aR[j] = *(const float4*)(aptr + k0 + j * 4);
            }
            gR = *(const float4*)(bgp + (size_t)k0 * IDIM);
            uR = *(const float4*)(bup + (size_t)k0 * IDIM);
        }
#pragma unroll
        for (int kk = 0; kk < 2; kk++) {
            uint32_t kb2 = kk * 32;
            uint32_t kbr = kk * 16 * ROWB;
            uint32_t ah[8], al[8];
#pragma unroll
            for (int mf = 0; mf < 2; mf++) {
                uint32_t ro = (uint32_t)(wm + mf * 16) * ROWB + aln + kb2;
                ldsm_x4(ah + mf * 4, uAh + ro);
                ldsm_x4(al + mf * 4, uAl + ro);
            }
#pragma unroll
            for (int nf = 0; nf < 2; nf++) {
                uint32_t co = kbr + bln + (uint32_t)(wn + nf * 8) * 2;
                uint32_t bgh[2], bgl[2], buh[2], bul[2];
                ldsm_x2t(bgh, uBgh + co);
                ldsm_x2t(bgl, uBgl + co);
                ldsm_x2t(buh, uBuh + co);
                ldsm_x2t(bul, uBul + co);
#pragma unroll
                for (int mf = 0; mf < 2; mf++) {
                    mma16816(accG[mf][nf], ah + mf * 4, bgh);
                    mma16816(accG[mf][nf], ah + mf * 4, bgl);
                    mma16816(accG[mf][nf], al + mf * 4, bgh);
                    mma16816(accU[mf][nf], ah + mf * 4, buh);
                    mma16816(accU[mf][nf], ah + mf * 4, bul);
                    mma16816(accU[mf][nf], al + mf * 4, buh);
                }
            }
        }
        __syncthreads();
    }

#pragma unroll
    for (int mf = 0; mf < 2; mf++)
#pragma unroll
        for (int nf = 0; nf < 2; nf++) {
            float* cg = accG[mf][nf];
            float* cu = accU[mf][nf];
            int ncol = col0 + wn + nf * 8 + 2 * q;
#pragma unroll
            for (int h = 0; h < 2; h++) {
                int lr = wm + mf * 16 + grp + h * 8;
                if (row0 + lr < M) {
                    int hr = s_hrow[lr];
                    float g0 = cg[h * 2 + 0], g1 = cg[h * 2 + 1];
                    float u0 = cu[h * 2 + 0], u1 = cu[h * 2 + 1];
                    float2 o;
                    o.x = g0 / (1.f + expf(-g0)) * u0;
                    o.y = g1 / (1.f + expf(-g1)) * u1;
                    *(float2*)(g_H + (size_t)hr * IDIM + ncol) = o;
                }
            }
        }
}

// ---- grouped GEMM 2: Y = H @ wd, split-bf16 3-pass HMMA -------------------
// NEW TILE: block 128x64, warp 32x32. grid (DDIM/64, NTOK/128, NEXP+1), 256 thr
__global__ void __launch_bounds__(256)
gemm2_kernel(const float* __restrict__ swd, const float* __restrict__ ewd) {
    __shared__ __align__(16) char sAh[128 * ROWB];
    __shared__ __align__(16) char sAl[128 * ROWB];
    __shared__ __align__(16) char sBh[KC * ROWB2];
    __shared__ __align__(16) char sBl[KC * ROWB2];
    __shared__ int s_hrow[128];

    int e = blockIdx.z;
    int M = (e == NEXP) ? NTOK : g_counts[e];
    int row0 = blockIdx.y * 128;
    if (row0 >= M) return;
    int col0 = blockIdx.x * 64;

    const float* wd = (e == NEXP) ? swd : ewd + (size_t)e * IDIM * DDIM;

    int tid = threadIdx.x, wid = tid >> 5, lane = tid & 31;
    if (tid < 128) {
        int r = row0 + tid;
        int hr = -1;
        if (r < M) {
            hr = (e == NEXP) ? (r * 3 + 2)
                             : (g_tok[e * NTOK + r] * 3 + g_slot[e * NTOK + r]);
        }
        s_hrow[tid] = hr;
    }
    __syncthreads();

    int arow = tid >> 1, ahalf = tid & 1;
    int btrow = tid >> 3, bcc = tid & 7;     // B: 32 rows x 64 cols, 8 floats/thread
    int ahr = s_hrow[arow];
    const float* aptr = g_H + (size_t)((ahr < 0) ? 0 : ahr) * IDIM + ahalf * 16;
    const float* bdp = wd + (size_t)btrow * DDIM + col0 + bcc * 8;

    float4 aR[4], dR0, dR1;
#pragma unroll
    for (int j = 0; j < 4; j++) aR[j] = make_float4(0.f, 0.f, 0.f, 0.f);
    if (ahr >= 0) {
#pragma unroll
        for (int j = 0; j < 4; j++) aR[j] = *(const float4*)(aptr + j * 4);
    }
    dR0 = *(const float4*)bdp;
    dR1 = *(const float4*)(bdp + 4);

    float acc[2][4][4];
#pragma unroll
    for (int a = 0; a < 2; a++)
#pragma unroll
        for (int b = 0; b < 4; b++)
#pragma unroll
            for (int c = 0; c < 4; c++) acc[a][b][c] = 0.f;

    int wm = (wid & 3) * 32, wn = (wid >> 2) * 32;
    int grp = lane >> 2, q = lane & 3;

    uint32_t uAh = smem_u32(sAh), uAl = smem_u32(sAl);
    uint32_t uBh = smem_u32(sBh), uBl = smem_u32(sBl);
    uint32_t aln  = (uint32_t)(lane & 15) * ROWB + ((lane >> 4) & 1) * 16;
    uint32_t bln2 = (uint32_t)(lane & 15) * ROWB2;

    const int NCHUNK = IDIM / KC;   // 16
    for (int c = 0; c < NCHUNK; c++) {
        {
            char* dah = sAh + arow * ROWB + ahalf * 32;
            char* dal = sAl + arow * ROWB + ahalf * 32;
#pragma unroll
            for (int j = 0; j < 4; j++) {
                uint2 p01 = splitpair(aR[j].x, aR[j].y);
                uint2 p23 = splitpair(aR[j].z, aR[j].w);
                *(uint32_t*)(dah + j * 8)     = p01.x;
                *(uint32_t*)(dah + j * 8 + 4) = p23.x;
                *(uint32_t*)(dal + j * 8)     = p01.y;
                *(uint32_t*)(dal + j * 8 + 4) = p23.y;
            }
            int db = btrow * ROWB2 + bcc * 16;
            uint2 d01 = splitpair(dR0.x, dR0.y), d23 = splitpair(dR0.z, dR0.w);
            uint2 d45 = splitpair(dR1.x, dR1.y), d67 = splitpair(dR1.z, dR1.w);
            *(uint32_t*)(sBh + db)      = d01.x;  *(uint32_t*)(sBh + db + 4)  = d23.x;
            *(uint32_t*)(sBh + db + 8)  = d45.x;  *(uint32_t*)(sBh + db + 12) = d67.x;
            *(uint32_t*)(sBl + db)      = d01.y;  *(uint32_t*)(sBl + db + 4)  = d23.y;
            *(uint32_t*)(sBl + db + 8)  = d45.y;  *(uint32_t*)(sBl + db + 12) = d67.y;
        }
        __syncthreads();
        if (c + 1 < NCHUNK) {
            int k0 = (c + 1) * KC;
            if (ahr >= 0) {
#pragma unroll
                for (int j = 0; j < 4; j++) aR[j] = *(const float4*)(aptr + k0 + j * 4);
            }
            dR0 = *(const float4*)(bdp + (size_t)k0 * DDIM);
            dR1 = *(const float4*)(bdp + (size_t)k0 * DDIM + 4);
        }
#pragma unroll
        for (int kk = 0; kk < 2; kk++) {
            uint32_t kb2 = kk * 32;
            uint32_t kbr2 = kk * 16 * ROWB2;
            uint32_t ah[8], al[8];
#pragma unroll
            for (int mf = 0; mf < 2; mf++) {
                uint32_t ro = (uint32_t)(wm + mf * 16) * ROWB + aln + kb2;
                ldsm_x4(ah + mf * 4, uAh + ro);
                ldsm_x4(al + mf * 4, uAl + ro);
            }
            uint32_t bh[8], bl[8];
#pragma unroll
            for (int nf = 0; nf < 4; nf++) {
                uint32_t co = kbr2 + bln2 + (uint32_t)(wn + nf * 8) * 2;
                ldsm_x2t(bh + nf * 2, uBh + co);
                ldsm_x2t(bl + nf * 2, uBl + co);
            }
#pragma unroll
            for (int nf = 0; nf < 4; nf++) {
#pragma unroll
                for (int mf = 0; mf < 2; mf++) {
                    mma16816(acc[mf][nf], ah + mf * 4, bh + nf * 2);
                    mma16816(acc[mf][nf], ah + mf * 4, bl + nf * 2);
                    mma16816(acc[mf][nf], al + mf * 4, bh + nf * 2);
                }
            }
        }
        __syncthreads();
    }

#pragma unroll
    for (int mf = 0; mf < 2; mf++)
#pragma unroll
        for (int nf = 0; nf < 4; nf++) {
            float* cc = acc[mf][nf];
            int ncol = col0 + wn + nf * 8 + 2 * q;
#pragma unroll
            for (int h = 0; h < 2; h++) {
                int lr = wm + mf * 16 + grp + h * 8;
                if (row0 + lr < M) {
                    int hr = s_hrow[lr];
                    float2 o = make_float2(cc[h * 2 + 0], cc[h * 2 + 1]);
                    *(float2*)(g_Y + (size_t)hr * DDIM + ncol) = o;
                }
            }
        }
}

// out = x + Y_shared + w0*Y_top0 + w1*Y_top1
__global__ void combine_kernel(const float* __restrict__ x, float* __restrict__ out) {
    int idx = blockIdx.x * blockDim.x + threadIdx.x;
    if (idx >= NTOK * DDIM / 4) return;
    int t = idx / (DDIM / 4);
    int dq = idx % (DDIM / 4);
    float w0 = g_w[t * 2 + 0], w1 = g_w[t * 2 + 1];
    float4 xv = ((const float4*)x)[idx];
    float4 y0 = *(const float4*)(g_Y + (size_t)(t * 3 + 0) * DDIM + dq * 4);
    float4 y1 = *(const float4*)(g_Y + (size_t)(t * 3 + 1) * DDIM + dq * 4);
    float4 y2 = *(const float4*)(g_Y + (size_t)(t * 3 + 2) * DDIM + dq * 4);
    float4 o;
    o.x = xv.x + y2.x + w0 * y0.x + w1 * y1.x;
    o.y = xv.y + y2.y + w0 * y0.y + w1 * y1.y;
    o.z = xv.z + y2.z + w0 * y0.z + w1 * y1.z;
    o.w = xv.w + y2.w + w0 * y0.w + w1 * y1.w;
    ((float4*)out)[idx] = o;
}

// ------------------------------------------------------------------ launch --
extern "C" void kernel_launch(void* const* d_in, const int* in_sizes, int n_in,
                              void* d_out, int out_size) {
    const float* x   = (const float*)d_in[0];
    const float* gw  = (const float*)d_in[1];
    const float* gb  = (const float*)d_in[2];
    const float* swg = (const float*)d_in[3];
    const float* swu = (const float*)d_in[4];
    const float* swd = (const float*)d_in[5];
    const float* ewg = (const float*)d_in[6];
    const float* ewu = (const float*)d_in[7];
    const float* ewd = (const float*)d_in[8];
    float* out = (float*)d_out;

    zero_counts_kernel<<<1, 32>>>();
    router_kernel<<<NTOK, 256>>>(x, gw, gb);

    gemm1_kernel<<<dim3(IDIM / 32, NTOK / 128, NEXP + 1), 256>>>(x, swg, swu, ewg, ewu);
    gemm2_kernel<<<dim3(DDIM / 64, NTOK / 128, NEXP + 1), 256>>>(swd, ewd);

    combine_kernel<<<(NTOK * DDIM / 4 + 255) / 256, 256>>>(x, out);
}